// round 11
// baseline (speedup 1.0000x reference)
#include <cuda_runtime.h>

// TVConv: per-pixel spatially-varying 3x3 depthwise conv.
// x:  (B=8, C=96, H=128, W=128) fp32
// wm: (1, C=96, 3, 3, H=128, W=128) fp32
// out[b,c,h,w] = sum_{ky,kx} wm[c,ky,kx,h,w] * x_pad[b,c,h+ky-1,w+kx-1]
//
// Strategy (HBM-bound problem, ~157MB mandatory traffic):
//  - Each thread owns 4 consecutive w-pixels (float4) of one (c,h) row.
//  - Loads its 9 per-pixel weight float4s ONCE into registers, then loops
//    over all 8 batch images (weight_maps batch dim is 1 -> 8x register
//    reuse, cuts weight DRAM traffic from 453MB to 57MB).
//  - Horizontal halo (w-1 / w+4) via warp shuffles; vertical halo via
//    predicated row loads (zero pad).
//  - blockDim (32,8): one warp per output row, 8 rows per CTA; adjacent
//    warps share x rows through L1; cross-CTA row re-reads hit L2
//    (entire x = 50MB fits in 126MB L2).

#define TV_B 8
#define TV_C 96
#define TV_H 128
#define TV_W 128

__global__ __launch_bounds__(256)
void tvconv_kernel(const float* __restrict__ x,
                   const float* __restrict__ wm,
                   float* __restrict__ out)
{
    const int lane = threadIdx.x;                 // 0..31
    const int h    = blockIdx.x * 8 + threadIdx.y;
    const int c    = blockIdx.y;
    const int w0   = lane * 4;

    const unsigned FULL = 0xffffffffu;
    const long HW = (long)TV_H * TV_W;

    // ---- load 9 per-pixel weight float4s into registers (reused for all b) ----
    float4 wt[9];
    {
        const long wbase = (long)c * 9 * HW + (long)h * TV_W + w0;
        #pragma unroll
        for (int t = 0; t < 9; t++) {
            wt[t] = *reinterpret_cast<const float4*>(wm + wbase + (long)t * HW);
        }
    }

    const long xrow = (long)h * TV_W + w0;        // offset within one (b,c) image

    #pragma unroll 4
    for (int b = 0; b < TV_B; b++) {
        const long xbase = ((long)(b * TV_C + c)) * HW + xrow;

        float4 acc = make_float4(0.f, 0.f, 0.f, 0.f);

        #pragma unroll
        for (int ky = 0; ky < 3; ky++) {
            const int hr = h + ky - 1;
            float4 v;
            if (hr >= 0 && hr < TV_H) {
                v = *reinterpret_cast<const float4*>(x + xbase + (long)(ky - 1) * TV_W);
            } else {
                v = make_float4(0.f, 0.f, 0.f, 0.f);
            }

            // horizontal halo via shuffles (zero at image edges)
            float vm1 = __shfl_up_sync(FULL, v.w, 1);   // value at w0-1
            if (lane == 0) vm1 = 0.f;
            float vp4 = __shfl_down_sync(FULL, v.x, 1); // value at w0+4
            if (lane == 31) vp4 = 0.f;

            const float4 wa = wt[ky * 3 + 0];  // kx = 0 (left tap)
            const float4 wb = wt[ky * 3 + 1];  // kx = 1 (center tap)
            const float4 wc = wt[ky * 3 + 2];  // kx = 2 (right tap)

            acc.x = fmaf(wa.x, vm1, fmaf(wb.x, v.x, fmaf(wc.x, v.y, acc.x)));
            acc.y = fmaf(wa.y, v.x, fmaf(wb.y, v.y, fmaf(wc.y, v.z, acc.y)));
            acc.z = fmaf(wa.z, v.y, fmaf(wb.z, v.z, fmaf(wc.z, v.w, acc.z)));
            acc.w = fmaf(wa.w, v.z, fmaf(wb.w, v.w, fmaf(wc.w, vp4, acc.w)));
        }

        *reinterpret_cast<float4*>(out + xbase) = acc;
    }
}

extern "C" void kernel_launch(void* const* d_in, const int* in_sizes, int n_in,
                              void* d_out, int out_size)
{
    const float* x  = (const float*)d_in[0];   // (8,96,128,128)
    const float* wm = (const float*)d_in[1];   // (1,96,3,3,128,128)
    float* out      = (float*)d_out;           // (8,96,128,128)

    dim3 block(32, 8);                         // one warp per row, 8 rows/CTA
    dim3 grid(TV_H / 8, TV_C);                 // (16, 96) = 1536 CTAs
    tvconv_kernel<<<grid, block>>>(x, wm, out);
}

// round 15
// speedup vs baseline: 1.1221x; 1.1221x over previous
#include <cuda_runtime.h>

// TVConv: per-pixel spatially-varying 3x3 depthwise conv.
// x:  (B=8, C=96, H=128, W=128) fp32
// wm: (1, C=96, 3, 3, H=128, W=128) fp32
// out[b,c,h,w] = sum_{ky,kx} wm[c,ky,kx,h,w] * x_pad[b,c,h+ky-1,w+kx-1]
//
// R11 evidence: latency-bound (HBM 53.5%, issue 22.5%, occ 41.8%, nothing
// saturated). This version software-pipelines the batch loop: prefetch the
// 3 x-rows of batch b+1 while computing batch b, full unroll, so each warp
// keeps independent DRAM loads in flight continuously. regs capped at 85
// via launch_bounds (3 CTAs/SM) -- trading a little occupancy for ~2x
// sustained MLP per warp.

#define TV_B 8
#define TV_C 96
#define TV_H 128
#define TV_W 128

__global__ __launch_bounds__(256, 3)
void tvconv_kernel(const float* __restrict__ x,
                   const float* __restrict__ wm,
                   float* __restrict__ out)
{
    const int lane = threadIdx.x;                 // 0..31
    const int h    = blockIdx.x * 8 + threadIdx.y;
    const int c    = blockIdx.y;
    const int w0   = lane * 4;

    const unsigned FULL = 0xffffffffu;
    const long HW = (long)TV_H * TV_W;
    const float4 Z = make_float4(0.f, 0.f, 0.f, 0.f);

    // ---- 9 per-pixel weight float4s in registers (reused for all 8 batches) ----
    float4 wt[9];
    {
        const long wbase = (long)c * 9 * HW + (long)h * TV_W + w0;
        #pragma unroll
        for (int t = 0; t < 9; t++)
            wt[t] = *reinterpret_cast<const float4*>(wm + wbase + (long)t * HW);
    }

    const bool hm = (h > 0);              // row h-1 exists
    const bool hp = (h < TV_H - 1);       // row h+1 exists
    const long xrow    = (long)h * TV_W + w0;
    const long xbase0  = (long)c * HW + xrow;      // batch 0
    const long bstride = (long)TV_C * HW;          // batch stride

    // ---- prologue: rows for batch 0 ----
    float4 v[3];
    v[0] = hm ? *reinterpret_cast<const float4*>(x + xbase0 - TV_W) : Z;
    v[1] =      *reinterpret_cast<const float4*>(x + xbase0);
    v[2] = hp ? *reinterpret_cast<const float4*>(x + xbase0 + TV_W) : Z;

    #pragma unroll
    for (int b = 0; b < TV_B; b++) {
        const long xbase = xbase0 + (long)b * bstride;

        // ---- prefetch rows for batch b+1 (issued before any compute) ----
        float4 n[3];
        if (b < TV_B - 1) {
            const long nb = xbase + bstride;
            n[0] = hm ? *reinterpret_cast<const float4*>(x + nb - TV_W) : Z;
            n[1] =      *reinterpret_cast<const float4*>(x + nb);
            n[2] = hp ? *reinterpret_cast<const float4*>(x + nb + TV_W) : Z;
        } else {
            n[0] = Z; n[1] = Z; n[2] = Z;
        }

        // ---- compute batch b from v[] ----
        float4 acc = Z;
        #pragma unroll
        for (int ky = 0; ky < 3; ky++) {
            const float4 vv = v[ky];
            float vm1 = __shfl_up_sync(FULL, vv.w, 1);   // pixel w0-1
            if (lane == 0) vm1 = 0.f;
            float vp4 = __shfl_down_sync(FULL, vv.x, 1); // pixel w0+4
            if (lane == 31) vp4 = 0.f;

            const float4 wa = wt[ky * 3 + 0];  // left tap
            const float4 wb = wt[ky * 3 + 1];  // center tap
            const float4 wc = wt[ky * 3 + 2];  // right tap

            acc.x = fmaf(wa.x, vm1,  fmaf(wb.x, vv.x, fmaf(wc.x, vv.y, acc.x)));
            acc.y = fmaf(wa.y, vv.x, fmaf(wb.y, vv.y, fmaf(wc.y, vv.z, acc.y)));
            acc.z = fmaf(wa.z, vv.y, fmaf(wb.z, vv.z, fmaf(wc.z, vv.w, acc.z)));
            acc.w = fmaf(wa.w, vv.z, fmaf(wb.w, vv.w, fmaf(wc.w, vp4,  acc.w)));
        }

        *reinterpret_cast<float4*>(out + xbase) = acc;

        // ---- rotate double buffer (register renaming, no moves after unroll) ----
        v[0] = n[0]; v[1] = n[1]; v[2] = n[2];
    }
}

extern "C" void kernel_launch(void* const* d_in, const int* in_sizes, int n_in,
                              void* d_out, int out_size)
{
    const float* x  = (const float*)d_in[0];   // (8,96,128,128)
    const float* wm = (const float*)d_in[1];   // (1,96,3,3,128,128)
    float* out      = (float*)d_out;           // (8,96,128,128)

    dim3 block(32, 8);                         // one warp per row, 8 rows/CTA
    dim3 grid(TV_H / 8, TV_C);                 // (16, 96) = 1536 CTAs
    tvconv_kernel<<<grid, block>>>(x, wm, out);
}